// round 7
// baseline (speedup 1.0000x reference)
#include <cuda_runtime.h>

typedef unsigned long long ull;

#define SEQ   1024
#define NBH   64
#define LOG2E 1.4426950408889634f

// rel_h / rel_w logit tables, pre-scaled by log2(e): [bh][s][k], k in 0..31
__device__ __align__(16) float g_relH[(size_t)NBH * SEQ * 32];
__device__ __align__(16) float g_relW[(size_t)NBH * SEQ * 32];

// ---------- f32x2 helpers ----------
__device__ __forceinline__ ull pack2(float x, float y) {
    ull r; asm("mov.b64 %0, {%1,%2};" : "=l"(r) : "f"(x), "f"(y)); return r;
}
__device__ __forceinline__ void unpack2(ull p, float& x, float& y) {
    asm("mov.b64 {%0,%1}, %2;" : "=f"(x), "=f"(y) : "l"(p));
}
__device__ __forceinline__ void fma2(ull& d, ull a, ull b) {
    asm("fma.rn.f32x2 %0, %1, %2, %0;" : "+l"(d) : "l"(a), "l"(b));
}
__device__ __forceinline__ ull mul2(ull a, ull b) {
    ull r; asm("mul.rn.f32x2 %0, %1, %2;" : "=l"(r) : "l"(a), "l"(b)); return r;
}
__device__ __forceinline__ float ex2f(float x) {
    float r; asm("ex2.approx.f32 %0, %1;" : "=f"(r) : "f"(x)); return r;
}

// ---------- kernel A: rel_h / rel_w precompute (smem-staged, tiled) ----------
__global__ void __launch_bounds__(256) rel_kernel(
    const float* __restrict__ q,
    const float* __restrict__ rph,
    const float* __restrict__ rpw)
{
    __shared__ float sQ[32 * 68];
    __shared__ float sRh[32 * 68];
    __shared__ float sRw[63 * 68];

    const int tid = threadIdx.x;
    const int h  = blockIdx.x;
    const int bh = blockIdx.y;
    const int b = bh >> 4, hd = bh & 15;

    {
        const int w = tid >> 3, c0 = (tid & 7) * 8;
        const float4* src = (const float4*)(q + ((size_t)(b * SEQ + h * 32 + w) * 16 + hd) * 64 + c0);
        *(float4*)(sQ + w * 68 + c0)     = src[0];
        *(float4*)(sQ + w * 68 + c0 + 4) = src[1];
        const float4* hs = (const float4*)(rph + (size_t)(h + 31 - w) * 64 + c0);
        *(float4*)(sRh + w * 68 + c0)     = hs[0];
        *(float4*)(sRh + w * 68 + c0 + 4) = hs[1];
    }
    for (int i = tid; i < 63 * 16; i += 256) {
        int r = i >> 4, c = (i & 15) * 4;
        *(float4*)(sRw + r * 68 + c) = *(const float4*)(rpw + (size_t)r * 64 + c);
    }
    __syncthreads();

    const int wid = tid >> 5, lane = tid & 31;   // lane = k
    #pragma unroll
    for (int rr = 0; rr < 4; rr++) {
        const int w = wid * 4 + rr;
        const float4* qv = (const float4*)(sQ + w * 68);
        const float4* hv = (const float4*)(sRh + lane * 68);
        const float4* wv = (const float4*)(sRw + (w + 31 - lane) * 68);
        float ah = 0.f, aw = 0.f;
        #pragma unroll
        for (int f = 0; f < 16; f++) {
            float4 a = qv[f], x = hv[f], y = wv[f];
            ah += a.x * x.x + a.y * x.y + a.z * x.z + a.w * x.w;
            aw += a.x * y.x + a.y * y.y + a.z * y.z + a.w * y.w;
        }
        size_t o = ((size_t)bh * SEQ + h * 32 + w) * 32 + lane;
        g_relH[o] = ah * LOG2E;
        g_relW[o] = aw * LOG2E;
    }
}

// ---------- kernel B: fp32 flash attention ----------
// block 128 (tx 0..15, ty 0..7); thread tile 8 m-rows x 4 n-cols (n = tx+16j),
// d-cols = {2tx,2tx+1, 2tx+32,2tx+33}. S paired over m; O paired over m
// (m-pairs 2i,2i+1); P stored TRANSPOSED Pt[n][m] as ull pairs.
// KP: K[n][c] stride 66 in QK, Pt[n][m] stride 66 in PV.
#define QT_S 64
#define KP_S 66
#define VS_S 68
#define RL_S 34

__global__ void __launch_bounds__(128, 3)
flash_kernel(const float* __restrict__ q, const float* __restrict__ k,
             const float* __restrict__ v, float* __restrict__ out)
{
    extern __shared__ float sm[];
    float* Qt = sm;                     // [64][64]  Qt[c][m] * 0.125*log2e
    float* KP = Qt + 64 * QT_S;         // [64][66]  K[n][c] in QK, Pt[n][m] in PV
    float* Vs = KP + 64 * KP_S;         // [64][68]  V[n][d]
    float* rH = Vs + 64 * VS_S;         // [64][34]
    float* rW = rH + 64 * RL_S;         // [64][34]

    const int tid = threadIdx.x;
    const int tx = tid & 15, ty = tid >> 4;
    const int mrow = ty * 8;
    const int m0 = blockIdx.x << 6;
    const int bh = blockIdx.y;
    const int b = bh >> 4, hd = bh & 15;

    const size_t hoff = (size_t)b * SEQ * 1024 + (size_t)hd * 64;
    const float* qh = q + hoff;
    const float* kh = k + hoff;
    const float* vh = v + hoff;
    float*       oh = out + hoff;

    const int lr = tid & 63;            // loader row
    const int lc = (tid >> 6) * 32;     // loader col base

    // ---- load Q tile transposed (scaled) + rel tables ----
    {
        const float qs = 0.125f * LOG2E;
        const float4* src = (const float4*)(qh + (size_t)(m0 + lr) * 1024 + lc);
        #pragma unroll
        for (int f = 0; f < 8; f++) {
            float4 x = src[f];
            const int c = lc + 4 * f;
            Qt[(c + 0) * QT_S + lr] = x.x * qs;
            Qt[(c + 1) * QT_S + lr] = x.y * qs;
            Qt[(c + 2) * QT_S + lr] = x.z * qs;
            Qt[(c + 3) * QT_S + lr] = x.w * qs;
        }
        const float4* rh4 = (const float4*)(g_relH + ((size_t)bh * SEQ + m0) * 32);
        const float4* rw4 = (const float4*)(g_relW + ((size_t)bh * SEQ + m0) * 32);
        #pragma unroll
        for (int f = 0; f < 4; f++) {
            const int gi = tid + f * 128;         // float4 index within 64x32
            const int m = gi >> 3, c4 = (gi & 7) * 4;
            float4 xh = rh4[gi];
            float4 xw = rw4[gi];
            rH[m * RL_S + c4 + 0] = xh.x; rH[m * RL_S + c4 + 1] = xh.y;
            rH[m * RL_S + c4 + 2] = xh.z; rH[m * RL_S + c4 + 3] = xh.w;
            rW[m * RL_S + c4 + 0] = xw.x; rW[m * RL_S + c4 + 1] = xw.y;
            rW[m * RL_S + c4 + 2] = xw.z; rW[m * RL_S + c4 + 3] = xw.w;
        }
    }

    // O accumulator: Om[mpair i][d-index u], ull lanes = rows (2i, 2i+1)
    // u: 0 -> d=2tx, 1 -> 2tx+1, 2 -> 2tx+32, 3 -> 2tx+33
    ull   Om[4][4];
    float rowm[8], rowl[8];
    #pragma unroll
    for (int i = 0; i < 4; i++) {
        Om[i][0] = 0ull; Om[i][1] = 0ull; Om[i][2] = 0ull; Om[i][3] = 0ull;
    }
    #pragma unroll
    for (int r = 0; r < 8; r++) { rowm[r] = -3.0e38f; rowl[r] = 0.f; }

    for (int n0 = 0; n0 < SEQ; n0 += 64) {
        __syncthreads();   // prev PV done with KP/Vs (iter 0: Qt/rel stores)
        // ---- load K row-major [n][c] (stride 66) + V natural (stride 68) ----
        {
            const float4* ks  = (const float4*)(kh + (size_t)(n0 + lr) * 1024 + lc);
            const float4* vs4 = (const float4*)(vh + (size_t)(n0 + lr) * 1024 + lc);
            float* kd = KP + lr * KP_S + lc;
            float* vd = Vs + lr * VS_S + lc;
            #pragma unroll
            for (int f = 0; f < 8; f++) {
                float4 kx = ks[f];
                *(float2*)(kd + 4 * f)     = make_float2(kx.x, kx.y);
                *(float2*)(kd + 4 * f + 2) = make_float2(kx.z, kx.w);
                *(float4*)(vd + 4 * f) = vs4[f];
            }
        }
        __syncthreads();

        // ---- S = Qs K^T : 8m x 4n, f32x2 paired over m ----
        ull Sa[4][4];
        #pragma unroll
        for (int i = 0; i < 4; i++)
            #pragma unroll
            for (int j = 0; j < 4; j++) Sa[i][j] = 0ull;

        #pragma unroll 8
        for (int c = 0; c < 64; c++) {
            const ulonglong2* qp = (const ulonglong2*)(Qt + c * QT_S + mrow);
            ulonglong2 qA = qp[0], qB = qp[1];
            const float* kp = KP + tx * KP_S + c;
            #pragma unroll
            for (int j = 0; j < 4; j++) {
                float bv = kp[16 * j * KP_S];          // K[tx+16j][c]
                ull bb = pack2(bv, bv);
                fma2(Sa[0][j], qA.x, bb);
                fma2(Sa[1][j], qA.y, bb);
                fma2(Sa[2][j], qB.x, bb);
                fma2(Sa[3][j], qB.y, bb);
            }
        }

        __syncthreads();   // all threads done reading KP as K

        // ---- softmax (2 rows at a time) + Pt store (transposed, ull pairs) ----
        const int kh0 = n0 >> 5;
        #pragma unroll
        for (int i = 0; i < 4; i++) {
            float s0[4], s1[4];
            #pragma unroll
            for (int j = 0; j < 4; j++) unpack2(Sa[i][j], s0[j], s1[j]);
            const int R0 = mrow + 2 * i, R1 = R0 + 1;
            // cols j=0..3 -> n = tx+16j: kh = kh0 + (j>=2), kw = tx + 16*(j&1)
            const float rhA0 = rH[R0 * RL_S + kh0],     rhB0 = rH[R0 * RL_S + kh0 + 1];
            const float rhA1 = rH[R1 * RL_S + kh0],     rhB1 = rH[R1 * RL_S + kh0 + 1];
            const float rwA0 = rW[R0 * RL_S + tx],      rwB0 = rW[R0 * RL_S + tx + 16];
            const float rwA1 = rW[R1 * RL_S + tx],      rwB1 = rW[R1 * RL_S + tx + 16];
            s0[0] += rhA0 + rwA0;  s0[1] += rhA0 + rwB0;
            s0[2] += rhB0 + rwA0;  s0[3] += rhB0 + rwB0;
            s1[0] += rhA1 + rwA1;  s1[1] += rhA1 + rwB1;
            s1[2] += rhB1 + rwA1;  s1[3] += rhB1 + rwB1;

            float mx0 = fmaxf(fmaxf(s0[0], s0[1]), fmaxf(s0[2], s0[3]));
            float mx1 = fmaxf(fmaxf(s1[0], s1[1]), fmaxf(s1[2], s1[3]));
            mx0 = fmaxf(mx0, __shfl_xor_sync(0xffffffffu, mx0, 1));
            mx0 = fmaxf(mx0, __shfl_xor_sync(0xffffffffu, mx0, 2));
            mx0 = fmaxf(mx0, __shfl_xor_sync(0xffffffffu, mx0, 4));
            mx0 = fmaxf(mx0, __shfl_xor_sync(0xffffffffu, mx0, 8));
            mx1 = fmaxf(mx1, __shfl_xor_sync(0xffffffffu, mx1, 1));
            mx1 = fmaxf(mx1, __shfl_xor_sync(0xffffffffu, mx1, 2));
            mx1 = fmaxf(mx1, __shfl_xor_sync(0xffffffffu, mx1, 4));
            mx1 = fmaxf(mx1, __shfl_xor_sync(0xffffffffu, mx1, 8));

            float mn0 = fmaxf(rowm[2 * i], mx0);
            float mn1 = fmaxf(rowm[2 * i + 1], mx1);
            float al0 = ex2f(rowm[2 * i] - mn0);
            float al1 = ex2f(rowm[2 * i + 1] - mn1);
            rowm[2 * i] = mn0; rowm[2 * i + 1] = mn1;
            ull alp = pack2(al0, al1);
            Om[i][0] = mul2(Om[i][0], alp);
            Om[i][1] = mul2(Om[i][1], alp);
            Om[i][2] = mul2(Om[i][2], alp);
            Om[i][3] = mul2(Om[i][3], alp);

            float ps0 = 0.f, ps1 = 0.f;
            #pragma unroll
            for (int j = 0; j < 4; j++) {
                float p0 = ex2f(s0[j] - mn0);
                float p1 = ex2f(s1[j] - mn1);
                ps0 += p0; ps1 += p1;
                *(ull*)(KP + (tx + 16 * j) * KP_S + R0) = pack2(p0, p1);
            }
            rowl[2 * i]     = rowl[2 * i] * al0 + ps0;
            rowl[2 * i + 1] = rowl[2 * i + 1] * al1 + ps1;
        }
        __syncthreads();

        // ---- O += P V : O paired over m, Pt broadcast reads ----
        #pragma unroll 8
        for (int n = 0; n < 64; n++) {
            const float* vrow = Vs + n * VS_S + 2 * tx;
            float v0, v1, v2, v3;
            unpack2(*(const ull*)vrow,        v0, v1);
            unpack2(*(const ull*)(vrow + 32), v2, v3);
            ull d0 = pack2(v0, v0), d1 = pack2(v1, v1);
            ull d2 = pack2(v2, v2), d3 = pack2(v3, v3);
            const ull* pp = (const ull*)(KP + n * KP_S + mrow);
            ull p0 = pp[0], p1 = pp[1], p2 = pp[2], p3 = pp[3];
            fma2(Om[0][0], p0, d0); fma2(Om[0][1], p0, d1);
            fma2(Om[0][2], p0, d2); fma2(Om[0][3], p0, d3);
            fma2(Om[1][0], p1, d0); fma2(Om[1][1], p1, d1);
            fma2(Om[1][2], p1, d2); fma2(Om[1][3], p1, d3);
            fma2(Om[2][0], p2, d0); fma2(Om[2][1], p2, d1);
            fma2(Om[2][2], p2, d2); fma2(Om[2][3], p2, d3);
            fma2(Om[3][0], p3, d0); fma2(Om[3][1], p3, d1);
            fma2(Om[3][2], p3, d2); fma2(Om[3][3], p3, d3);
        }
    }

    // ---- finalize ----
    #pragma unroll
    for (int r = 0; r < 8; r++) {
        float l = rowl[r];
        l += __shfl_xor_sync(0xffffffffu, l, 1);
        l += __shfl_xor_sync(0xffffffffu, l, 2);
        l += __shfl_xor_sync(0xffffffffu, l, 4);
        l += __shfl_xor_sync(0xffffffffu, l, 8);
        rowl[r] = __fdividef(1.0f, l);
    }
    #pragma unroll
    for (int i = 0; i < 4; i++) {
        const float inv0 = rowl[2 * i], inv1 = rowl[2 * i + 1];
        float o00, o10, o01, o11, o02, o12, o03, o13;
        unpack2(Om[i][0], o00, o10);
        unpack2(Om[i][1], o01, o11);
        unpack2(Om[i][2], o02, o12);
        unpack2(Om[i][3], o03, o13);
        float* op0 = oh + (size_t)(m0 + mrow + 2 * i) * 1024 + 2 * tx;
        float* op1 = op0 + 1024;
        *(float2*)op0        = make_float2(o00 * inv0, o01 * inv0);
        *(float2*)(op0 + 32) = make_float2(o02 * inv0, o03 * inv0);
        *(float2*)op1        = make_float2(o10 * inv1, o11 * inv1);
        *(float2*)(op1 + 32) = make_float2(o12 * inv1, o13 * inv1);
    }
}

extern "C" void kernel_launch(void* const* d_in, const int* in_sizes, int n_in,
                              void* d_out, int out_size)
{
    const float* q   = (const float*)d_in[0];
    const float* k   = (const float*)d_in[1];
    const float* v   = (const float*)d_in[2];
    const float* rph = (const float*)d_in[3];
    const float* rpw = (const float*)d_in[4];
    float* out = (float*)d_out;

    dim3 rg(32, 64);
    rel_kernel<<<rg, 256>>>(q, rph, rpw);

    const int smem = (64 * QT_S + 64 * KP_S + 64 * VS_S + 64 * RL_S * 2) * 4; // 68096 B
    cudaFuncSetAttribute(flash_kernel, cudaFuncAttributeMaxDynamicSharedMemorySize, smem);
    dim3 grid(SEQ / 64, NBH);
    flash_kernel<<<grid, 128, smem>>>(q, k, v, out);
}

// round 8
// speedup vs baseline: 1.0008x; 1.0008x over previous
#include <cuda_runtime.h>

typedef unsigned long long ull;

#define SEQ   1024
#define NBH   64
#define LOG2E 1.4426950408889634f

// rel_h / rel_w logit tables, pre-scaled by log2(e): [bh][s][k], k in 0..31
__device__ __align__(16) float g_relH[(size_t)NBH * SEQ * 32];
__device__ __align__(16) float g_relW[(size_t)NBH * SEQ * 32];

// ---------- f32x2 helpers ----------
__device__ __forceinline__ ull pack2(float x, float y) {
    ull r; asm("mov.b64 %0, {%1,%2};" : "=l"(r) : "f"(x), "f"(y)); return r;
}
__device__ __forceinline__ void unpack2(ull p, float& x, float& y) {
    asm("mov.b64 {%0,%1}, %2;" : "=f"(x), "=f"(y) : "l"(p));
}
__device__ __forceinline__ void fma2(ull& d, ull a, ull b) {
    asm("fma.rn.f32x2 %0, %1, %2, %0;" : "+l"(d) : "l"(a), "l"(b));
}
__device__ __forceinline__ ull mul2(ull a, ull b) {
    ull r; asm("mul.rn.f32x2 %0, %1, %2;" : "=l"(r) : "l"(a), "l"(b)); return r;
}
__device__ __forceinline__ float ex2f(float x) {
    float r; asm("ex2.approx.f32 %0, %1;" : "=f"(r) : "f"(x)); return r;
}

// ---------- kernel A: rel_h / rel_w precompute (smem-staged, tiled) ----------
__global__ void __launch_bounds__(256) rel_kernel(
    const float* __restrict__ q,
    const float* __restrict__ rph,
    const float* __restrict__ rpw)
{
    __shared__ float sQ[32 * 68];
    __shared__ float sRh[32 * 68];
    __shared__ float sRw[63 * 68];

    const int tid = threadIdx.x;
    const int h  = blockIdx.x;
    const int bh = blockIdx.y;
    const int b = bh >> 4, hd = bh & 15;

    {
        const int w = tid >> 3, c0 = (tid & 7) * 8;
        const float4* src = (const float4*)(q + ((size_t)(b * SEQ + h * 32 + w) * 16 + hd) * 64 + c0);
        *(float4*)(sQ + w * 68 + c0)     = src[0];
        *(float4*)(sQ + w * 68 + c0 + 4) = src[1];
        const float4* hs = (const float4*)(rph + (size_t)(h + 31 - w) * 64 + c0);
        *(float4*)(sRh + w * 68 + c0)     = hs[0];
        *(float4*)(sRh + w * 68 + c0 + 4) = hs[1];
    }
    for (int i = tid; i < 63 * 16; i += 256) {
        int r = i >> 4, c = (i & 15) * 4;
        *(float4*)(sRw + r * 68 + c) = *(const float4*)(rpw + (size_t)r * 64 + c);
    }
    __syncthreads();

    const int wid = tid >> 5, lane = tid & 31;   // lane = k
    #pragma unroll
    for (int rr = 0; rr < 4; rr++) {
        const int w = wid * 4 + rr;
        const float4* qv = (const float4*)(sQ + w * 68);
        const float4* hv = (const float4*)(sRh + lane * 68);
        const float4* wv = (const float4*)(sRw + (w + 31 - lane) * 68);
        float ah = 0.f, aw = 0.f;
        #pragma unroll
        for (int f = 0; f < 16; f++) {
            float4 a = qv[f], x = hv[f], y = wv[f];
            ah += a.x * x.x + a.y * x.y + a.z * x.z + a.w * x.w;
            aw += a.x * y.x + a.y * y.y + a.z * y.z + a.w * y.w;
        }
        size_t o = ((size_t)bh * SEQ + h * 32 + w) * 32 + lane;
        g_relH[o] = ah * LOG2E;
        g_relW[o] = aw * LOG2E;
    }
}

// ---------- kernel B: fp32 flash attention ----------
// block 128 (tx 0..15, ty 0..7); thread tile 8 m-rows x 4 n-cols (n = tx+16j),
// d-cols = {2tx,2tx+1, 2tx+32,2tx+33}. S paired over m; O paired over m
// (m-pairs 2i,2i+1); P stored TRANSPOSED Pt[n][m] as ull pairs.
// KP: K[n][c] stride 66 in QK, Pt[n][m] stride 66 in PV.
#define QT_S 64
#define KP_S 66
#define VS_S 68
#define RL_S 34

__global__ void __launch_bounds__(128, 3)
flash_kernel(const float* __restrict__ q, const float* __restrict__ k,
             const float* __restrict__ v, float* __restrict__ out)
{
    extern __shared__ float sm[];
    float* Qt = sm;                     // [64][64]  Qt[c][m] * 0.125*log2e
    float* KP = Qt + 64 * QT_S;         // [64][66]  K[n][c] in QK, Pt[n][m] in PV
    float* Vs = KP + 64 * KP_S;         // [64][68]  V[n][d]
    float* rH = Vs + 64 * VS_S;         // [64][34]
    float* rW = rH + 64 * RL_S;         // [64][34]

    const int tid = threadIdx.x;
    const int tx = tid & 15, ty = tid >> 4;
    const int mrow = ty * 8;
    const int m0 = blockIdx.x << 6;
    const int bh = blockIdx.y;
    const int b = bh >> 4, hd = bh & 15;

    const size_t hoff = (size_t)b * SEQ * 1024 + (size_t)hd * 64;
    const float* qh = q + hoff;
    const float* kh = k + hoff;
    const float* vh = v + hoff;
    float*       oh = out + hoff;

    const int lr = tid & 63;            // loader row
    const int lc = (tid >> 6) * 32;     // loader col base

    // ---- load Q tile transposed (scaled) + rel tables ----
    {
        const float qs = 0.125f * LOG2E;
        const float4* src = (const float4*)(qh + (size_t)(m0 + lr) * 1024 + lc);
        #pragma unroll
        for (int f = 0; f < 8; f++) {
            float4 x = src[f];
            const int c = lc + 4 * f;
            Qt[(c + 0) * QT_S + lr] = x.x * qs;
            Qt[(c + 1) * QT_S + lr] = x.y * qs;
            Qt[(c + 2) * QT_S + lr] = x.z * qs;
            Qt[(c + 3) * QT_S + lr] = x.w * qs;
        }
        const float4* rh4 = (const float4*)(g_relH + ((size_t)bh * SEQ + m0) * 32);
        const float4* rw4 = (const float4*)(g_relW + ((size_t)bh * SEQ + m0) * 32);
        #pragma unroll
        for (int f = 0; f < 4; f++) {
            const int gi = tid + f * 128;         // float4 index within 64x32
            const int m = gi >> 3, c4 = (gi & 7) * 4;
            float4 xh = rh4[gi];
            float4 xw = rw4[gi];
            rH[m * RL_S + c4 + 0] = xh.x; rH[m * RL_S + c4 + 1] = xh.y;
            rH[m * RL_S + c4 + 2] = xh.z; rH[m * RL_S + c4 + 3] = xh.w;
            rW[m * RL_S + c4 + 0] = xw.x; rW[m * RL_S + c4 + 1] = xw.y;
            rW[m * RL_S + c4 + 2] = xw.z; rW[m * RL_S + c4 + 3] = xw.w;
        }
    }

    // O accumulator: Om[mpair i][d-index u], ull lanes = rows (2i, 2i+1)
    // u: 0 -> d=2tx, 1 -> 2tx+1, 2 -> 2tx+32, 3 -> 2tx+33
    ull   Om[4][4];
    float rowm[8], rowl[8];
    #pragma unroll
    for (int i = 0; i < 4; i++) {
        Om[i][0] = 0ull; Om[i][1] = 0ull; Om[i][2] = 0ull; Om[i][3] = 0ull;
    }
    #pragma unroll
    for (int r = 0; r < 8; r++) { rowm[r] = -3.0e38f; rowl[r] = 0.f; }

    for (int n0 = 0; n0 < SEQ; n0 += 64) {
        __syncthreads();   // prev PV done with KP/Vs (iter 0: Qt/rel stores)
        // ---- load K row-major [n][c] (stride 66) + V natural (stride 68) ----
        {
            const float4* ks  = (const float4*)(kh + (size_t)(n0 + lr) * 1024 + lc);
            const float4* vs4 = (const float4*)(vh + (size_t)(n0 + lr) * 1024 + lc);
            float* kd = KP + lr * KP_S + lc;
            float* vd = Vs + lr * VS_S + lc;
            #pragma unroll
            for (int f = 0; f < 8; f++) {
                float4 kx = ks[f];
                *(float2*)(kd + 4 * f)     = make_float2(kx.x, kx.y);
                *(float2*)(kd + 4 * f + 2) = make_float2(kx.z, kx.w);
                *(float4*)(vd + 4 * f) = vs4[f];
            }
        }
        __syncthreads();

        // ---- S = Qs K^T : 8m x 4n, f32x2 paired over m ----
        ull Sa[4][4];
        #pragma unroll
        for (int i = 0; i < 4; i++)
            #pragma unroll
            for (int j = 0; j < 4; j++) Sa[i][j] = 0ull;

        #pragma unroll 8
        for (int c = 0; c < 64; c++) {
            const ulonglong2* qp = (const ulonglong2*)(Qt + c * QT_S + mrow);
            ulonglong2 qA = qp[0], qB = qp[1];
            const float* kp = KP + tx * KP_S + c;
            #pragma unroll
            for (int j = 0; j < 4; j++) {
                float bv = kp[16 * j * KP_S];          // K[tx+16j][c]
                ull bb = pack2(bv, bv);
                fma2(Sa[0][j], qA.x, bb);
                fma2(Sa[1][j], qA.y, bb);
                fma2(Sa[2][j], qB.x, bb);
                fma2(Sa[3][j], qB.y, bb);
            }
        }

        __syncthreads();   // all threads done reading KP as K

        // ---- softmax (2 rows at a time) + Pt store (transposed, ull pairs) ----
        const int kh0 = n0 >> 5;
        #pragma unroll
        for (int i = 0; i < 4; i++) {
            float s0[4], s1[4];
            #pragma unroll
            for (int j = 0; j < 4; j++) unpack2(Sa[i][j], s0[j], s1[j]);
            const int R0 = mrow + 2 * i, R1 = R0 + 1;
            // cols j=0..3 -> n = tx+16j: kh = kh0 + (j>=2), kw = tx + 16*(j&1)
            const float rhA0 = rH[R0 * RL_S + kh0],     rhB0 = rH[R0 * RL_S + kh0 + 1];
            const float rhA1 = rH[R1 * RL_S + kh0],     rhB1 = rH[R1 * RL_S + kh0 + 1];
            const float rwA0 = rW[R0 * RL_S + tx],      rwB0 = rW[R0 * RL_S + tx + 16];
            const float rwA1 = rW[R1 * RL_S + tx],      rwB1 = rW[R1 * RL_S + tx + 16];
            s0[0] += rhA0 + rwA0;  s0[1] += rhA0 + rwB0;
            s0[2] += rhB0 + rwA0;  s0[3] += rhB0 + rwB0;
            s1[0] += rhA1 + rwA1;  s1[1] += rhA1 + rwB1;
            s1[2] += rhB1 + rwA1;  s1[3] += rhB1 + rwB1;

            float mx0 = fmaxf(fmaxf(s0[0], s0[1]), fmaxf(s0[2], s0[3]));
            float mx1 = fmaxf(fmaxf(s1[0], s1[1]), fmaxf(s1[2], s1[3]));
            mx0 = fmaxf(mx0, __shfl_xor_sync(0xffffffffu, mx0, 1));
            mx0 = fmaxf(mx0, __shfl_xor_sync(0xffffffffu, mx0, 2));
            mx0 = fmaxf(mx0, __shfl_xor_sync(0xffffffffu, mx0, 4));
            mx0 = fmaxf(mx0, __shfl_xor_sync(0xffffffffu, mx0, 8));
            mx1 = fmaxf(mx1, __shfl_xor_sync(0xffffffffu, mx1, 1));
            mx1 = fmaxf(mx1, __shfl_xor_sync(0xffffffffu, mx1, 2));
            mx1 = fmaxf(mx1, __shfl_xor_sync(0xffffffffu, mx1, 4));
            mx1 = fmaxf(mx1, __shfl_xor_sync(0xffffffffu, mx1, 8));

            float mn0 = fmaxf(rowm[2 * i], mx0);
            float mn1 = fmaxf(rowm[2 * i + 1], mx1);
            float al0 = ex2f(rowm[2 * i] - mn0);
            float al1 = ex2f(rowm[2 * i + 1] - mn1);
            rowm[2 * i] = mn0; rowm[2 * i + 1] = mn1;
            ull alp = pack2(al0, al1);
            Om[i][0] = mul2(Om[i][0], alp);
            Om[i][1] = mul2(Om[i][1], alp);
            Om[i][2] = mul2(Om[i][2], alp);
            Om[i][3] = mul2(Om[i][3], alp);

            float ps0 = 0.f, ps1 = 0.f;
            #pragma unroll
            for (int j = 0; j < 4; j++) {
                float p0 = ex2f(s0[j] - mn0);
                float p1 = ex2f(s1[j] - mn1);
                ps0 += p0; ps1 += p1;
                *(ull*)(KP + (tx + 16 * j) * KP_S + R0) = pack2(p0, p1);
            }
            rowl[2 * i]     = rowl[2 * i] * al0 + ps0;
            rowl[2 * i + 1] = rowl[2 * i + 1] * al1 + ps1;
        }
        __syncthreads();

        // ---- O += P V : O paired over m, Pt broadcast reads ----
        #pragma unroll 8
        for (int n = 0; n < 64; n++) {
            const float* vrow = Vs + n * VS_S + 2 * tx;
            float v0, v1, v2, v3;
            unpack2(*(const ull*)vrow,        v0, v1);
            unpack2(*(const ull*)(vrow + 32), v2, v3);
            ull d0 = pack2(v0, v0), d1 = pack2(v1, v1);
            ull d2 = pack2(v2, v2), d3 = pack2(v3, v3);
            const ull* pp = (const ull*)(KP + n * KP_S + mrow);
            ull p0 = pp[0], p1 = pp[1], p2 = pp[2], p3 = pp[3];
            fma2(Om[0][0], p0, d0); fma2(Om[0][1], p0, d1);
            fma2(Om[0][2], p0, d2); fma2(Om[0][3], p0, d3);
            fma2(Om[1][0], p1, d0); fma2(Om[1][1], p1, d1);
            fma2(Om[1][2], p1, d2); fma2(Om[1][3], p1, d3);
            fma2(Om[2][0], p2, d0); fma2(Om[2][1], p2, d1);
            fma2(Om[2][2], p2, d2); fma2(Om[2][3], p2, d3);
            fma2(Om[3][0], p3, d0); fma2(Om[3][1], p3, d1);
            fma2(Om[3][2], p3, d2); fma2(Om[3][3], p3, d3);
        }
    }

    // ---- finalize ----
    #pragma unroll
    for (int r = 0; r < 8; r++) {
        float l = rowl[r];
        l += __shfl_xor_sync(0xffffffffu, l, 1);
        l += __shfl_xor_sync(0xffffffffu, l, 2);
        l += __shfl_xor_sync(0xffffffffu, l, 4);
        l += __shfl_xor_sync(0xffffffffu, l, 8);
        rowl[r] = __fdividef(1.0f, l);
    }
    #pragma unroll
    for (int i = 0; i < 4; i++) {
        const float inv0 = rowl[2 * i], inv1 = rowl[2 * i + 1];
        float o00, o10, o01, o11, o02, o12, o03, o13;
        unpack2(Om[i][0], o00, o10);
        unpack2(Om[i][1], o01, o11);
        unpack2(Om[i][2], o02, o12);
        unpack2(Om[i][3], o03, o13);
        float* op0 = oh + (size_t)(m0 + mrow + 2 * i) * 1024 + 2 * tx;
        float* op1 = op0 + 1024;
        *(float2*)op0        = make_float2(o00 * inv0, o01 * inv0);
        *(float2*)(op0 + 32) = make_float2(o02 * inv0, o03 * inv0);
        *(float2*)op1        = make_float2(o10 * inv1, o11 * inv1);
        *(float2*)(op1 + 32) = make_float2(o12 * inv1, o13 * inv1);
    }
}

extern "C" void kernel_launch(void* const* d_in, const int* in_sizes, int n_in,
                              void* d_out, int out_size)
{
    const float* q   = (const float*)d_in[0];
    const float* k   = (const float*)d_in[1];
    const float* v   = (const float*)d_in[2];
    const float* rph = (const float*)d_in[3];
    const float* rpw = (const float*)d_in[4];
    float* out = (float*)d_out;

    dim3 rg(32, 64);
    rel_kernel<<<rg, 256>>>(q, rph, rpw);

    const int smem = (64 * QT_S + 64 * KP_S + 64 * VS_S + 64 * RL_S * 2) * 4; // 68096 B
    cudaFuncSetAttribute(flash_kernel, cudaFuncAttributeMaxDynamicSharedMemorySize, smem);
    dim3 grid(SEQ / 64, NBH);
    flash_kernel<<<grid, 128, smem>>>(q, k, v, out);
}

// round 9
// speedup vs baseline: 1.0013x; 1.0005x over previous
#include <cuda_runtime.h>

typedef unsigned long long ull;

#define SEQ   1024
#define NBH   64
#define LOG2E 1.4426950408889634f

// rel_h / rel_w logit tables, pre-scaled by log2(e): [bh][s][k], k in 0..31
__device__ __align__(16) float g_relH[(size_t)NBH * SEQ * 32];
__device__ __align__(16) float g_relW[(size_t)NBH * SEQ * 32];

// ---------- f32x2 helpers ----------
__device__ __forceinline__ ull pack2(float x, float y) {
    ull r; asm("mov.b64 %0, {%1,%2};" : "=l"(r) : "f"(x), "f"(y)); return r;
}
__device__ __forceinline__ void unpack2(ull p, float& x, float& y) {
    asm("mov.b64 {%0,%1}, %2;" : "=f"(x), "=f"(y) : "l"(p));
}
__device__ __forceinline__ void fma2(ull& d, ull a, ull b) {
    asm("fma.rn.f32x2 %0, %1, %2, %0;" : "+l"(d) : "l"(a), "l"(b));
}
__device__ __forceinline__ ull mul2(ull a, ull b) {
    ull r; asm("mul.rn.f32x2 %0, %1, %2;" : "=l"(r) : "l"(a), "l"(b)); return r;
}
__device__ __forceinline__ float ex2f(float x) {
    float r; asm("ex2.approx.f32 %0, %1;" : "=f"(r) : "f"(x)); return r;
}

// ---------- kernel A: rel_h / rel_w precompute (smem-staged, tiled) ----------
__global__ void __launch_bounds__(256) rel_kernel(
    const float* __restrict__ q,
    const float* __restrict__ rph,
    const float* __restrict__ rpw)
{
    __shared__ float sQ[32 * 68];
    __shared__ float sRh[32 * 68];
    __shared__ float sRw[63 * 68];

    const int tid = threadIdx.x;
    const int h  = blockIdx.x;
    const int bh = blockIdx.y;
    const int b = bh >> 4, hd = bh & 15;

    {
        const int w = tid >> 3, c0 = (tid & 7) * 8;
        const float4* src = (const float4*)(q + ((size_t)(b * SEQ + h * 32 + w) * 16 + hd) * 64 + c0);
        *(float4*)(sQ + w * 68 + c0)     = src[0];
        *(float4*)(sQ + w * 68 + c0 + 4) = src[1];
        const float4* hs = (const float4*)(rph + (size_t)(h + 31 - w) * 64 + c0);
        *(float4*)(sRh + w * 68 + c0)     = hs[0];
        *(float4*)(sRh + w * 68 + c0 + 4) = hs[1];
    }
    for (int i = tid; i < 63 * 16; i += 256) {
        int r = i >> 4, c = (i & 15) * 4;
        *(float4*)(sRw + r * 68 + c) = *(const float4*)(rpw + (size_t)r * 64 + c);
    }
    __syncthreads();

    const int wid = tid >> 5, lane = tid & 31;   // lane = k
    #pragma unroll
    for (int rr = 0; rr < 4; rr++) {
        const int w = wid * 4 + rr;
        const float4* qv = (const float4*)(sQ + w * 68);
        const float4* hv = (const float4*)(sRh + lane * 68);
        const float4* wv = (const float4*)(sRw + (w + 31 - lane) * 68);
        float ah = 0.f, aw = 0.f;
        #pragma unroll
        for (int f = 0; f < 16; f++) {
            float4 a = qv[f], x = hv[f], y = wv[f];
            ah += a.x * x.x + a.y * x.y + a.z * x.z + a.w * x.w;
            aw += a.x * y.x + a.y * y.y + a.z * y.z + a.w * y.w;
        }
        size_t o = ((size_t)bh * SEQ + h * 32 + w) * 32 + lane;
        g_relH[o] = ah * LOG2E;
        g_relW[o] = aw * LOG2E;
    }
}

// ---------- kernel B: fp32 flash attention ----------
// block 128 (tx 0..15, ty 0..7); thread tile 8 m-rows x 4 n-cols (n = tx+16j),
// d-cols = {2tx,2tx+1, 2tx+32,2tx+33}. S paired over m; O paired over m;
// P stored TRANSPOSED Pt[n][m] as ull pairs. QK c-blocked by 2, K read LDS.64.
#define QT_S 64
#define KP_S 66
#define VS_S 68
#define RL_S 34

__global__ void __launch_bounds__(128, 3)
flash_kernel(const float* __restrict__ q, const float* __restrict__ k,
             const float* __restrict__ v, float* __restrict__ out)
{
    extern __shared__ float sm[];
    float* Qt = sm;                     // [64][64]  Qt[c][m] * 0.125*log2e
    float* KP = Qt + 64 * QT_S;         // [64][66]  K[n][c] in QK, Pt[n][m] in PV
    float* Vs = KP + 64 * KP_S;         // [64][68]  V[n][d]
    float* rH = Vs + 64 * VS_S;         // [64][34]
    float* rW = rH + 64 * RL_S;         // [64][34]

    const int tid = threadIdx.x;
    const int tx = tid & 15, ty = tid >> 4;
    const int mrow = ty * 8;
    const int m0 = blockIdx.x << 6;
    const int bh = blockIdx.y;
    const int b = bh >> 4, hd = bh & 15;

    const size_t hoff = (size_t)b * SEQ * 1024 + (size_t)hd * 64;
    const float* qh = q + hoff;
    const float* kh = k + hoff;
    const float* vh = v + hoff;
    float*       oh = out + hoff;

    const int lr = tid & 63;            // loader row
    const int lc = (tid >> 6) * 32;     // loader col base

    // ---- load Q tile transposed (scaled) + rel tables ----
    {
        const float qs = 0.125f * LOG2E;
        const float4* src = (const float4*)(qh + (size_t)(m0 + lr) * 1024 + lc);
        #pragma unroll
        for (int f = 0; f < 8; f++) {
            float4 x = src[f];
            const int c = lc + 4 * f;
            Qt[(c + 0) * QT_S + lr] = x.x * qs;
            Qt[(c + 1) * QT_S + lr] = x.y * qs;
            Qt[(c + 2) * QT_S + lr] = x.z * qs;
            Qt[(c + 3) * QT_S + lr] = x.w * qs;
        }
        const float4* rh4 = (const float4*)(g_relH + ((size_t)bh * SEQ + m0) * 32);
        const float4* rw4 = (const float4*)(g_relW + ((size_t)bh * SEQ + m0) * 32);
        #pragma unroll
        for (int f = 0; f < 4; f++) {
            const int gi = tid + f * 128;         // float4 index within 64x32
            const int m = gi >> 3, c4 = (gi & 7) * 4;
            float4 xh = rh4[gi];
            float4 xw = rw4[gi];
            rH[m * RL_S + c4 + 0] = xh.x; rH[m * RL_S + c4 + 1] = xh.y;
            rH[m * RL_S + c4 + 2] = xh.z; rH[m * RL_S + c4 + 3] = xh.w;
            rW[m * RL_S + c4 + 0] = xw.x; rW[m * RL_S + c4 + 1] = xw.y;
            rW[m * RL_S + c4 + 2] = xw.z; rW[m * RL_S + c4 + 3] = xw.w;
        }
    }

    // O accumulator: Om[mpair i][d-index u], ull lanes = rows (2i, 2i+1)
    ull   Om[4][4];
    float rowm[8], rowl[8];
    #pragma unroll
    for (int i = 0; i < 4; i++) {
        Om[i][0] = 0ull; Om[i][1] = 0ull; Om[i][2] = 0ull; Om[i][3] = 0ull;
    }
    #pragma unroll
    for (int r = 0; r < 8; r++) { rowm[r] = -3.0e38f; rowl[r] = 0.f; }

    for (int n0 = 0; n0 < SEQ; n0 += 64) {
        __syncthreads();   // prev PV done with KP/Vs (iter 0: Qt/rel stores)
        // ---- load K row-major [n][c] (stride 66) + V natural (stride 68) ----
        {
            const float4* ks  = (const float4*)(kh + (size_t)(n0 + lr) * 1024 + lc);
            const float4* vs4 = (const float4*)(vh + (size_t)(n0 + lr) * 1024 + lc);
            float* kd = KP + lr * KP_S + lc;
            float* vd = Vs + lr * VS_S + lc;
            #pragma unroll
            for (int f = 0; f < 8; f++) {
                float4 kx = ks[f];
                *(float2*)(kd + 4 * f)     = make_float2(kx.x, kx.y);
                *(float2*)(kd + 4 * f + 2) = make_float2(kx.z, kx.w);
                *(float4*)(vd + 4 * f) = vs4[f];
            }
        }
        __syncthreads();

        // ---- S = Qs K^T : 8m x 4n, f32x2 paired over m, c-blocked by 2 ----
        ull Sa[4][4];
        #pragma unroll
        for (int i = 0; i < 4; i++)
            #pragma unroll
            for (int j = 0; j < 4; j++) Sa[i][j] = 0ull;

        #pragma unroll 4
        for (int c = 0; c < 64; c += 2) {
            const ulonglong2* qp0 = (const ulonglong2*)(Qt + c * QT_S + mrow);
            const ulonglong2* qp1 = (const ulonglong2*)(Qt + (c + 1) * QT_S + mrow);
            ulonglong2 qA0 = qp0[0], qB0 = qp0[1];
            ulonglong2 qA1 = qp1[0], qB1 = qp1[1];
            const float* kp = KP + tx * KP_S + c;
            #pragma unroll
            for (int j = 0; j < 4; j++) {
                float2 kv = *(const float2*)(kp + 16 * j * KP_S);   // K[tx+16j][c..c+1]
                ull b0 = pack2(kv.x, kv.x);
                ull b1 = pack2(kv.y, kv.y);
                fma2(Sa[0][j], qA0.x, b0);
                fma2(Sa[1][j], qA0.y, b0);
                fma2(Sa[2][j], qB0.x, b0);
                fma2(Sa[3][j], qB0.y, b0);
                fma2(Sa[0][j], qA1.x, b1);
                fma2(Sa[1][j], qA1.y, b1);
                fma2(Sa[2][j], qB1.x, b1);
                fma2(Sa[3][j], qB1.y, b1);
            }
        }

        __syncthreads();   // all threads done reading KP as K

        // ---- softmax (2 rows at a time) + Pt store (transposed, ull pairs) ----
        const int kh0 = n0 >> 5;
        #pragma unroll
        for (int i = 0; i < 4; i++) {
            float s0[4], s1[4];
            #pragma unroll
            for (int j = 0; j < 4; j++) unpack2(Sa[i][j], s0[j], s1[j]);
            const int R0 = mrow + 2 * i, R1 = R0 + 1;
            // cols j=0..3 -> n = tx+16j: kh = kh0 + (j>=2), kw = tx + 16*(j&1)
            const float rhA0 = rH[R0 * RL_S + kh0],     rhB0 = rH[R0 * RL_S + kh0 + 1];
            const float rhA1 = rH[R1 * RL_S + kh0],     rhB1 = rH[R1 * RL_S + kh0 + 1];
            const float rwA0 = rW[R0 * RL_S + tx],      rwB0 = rW[R0 * RL_S + tx + 16];
            const float rwA1 = rW[R1 * RL_S + tx],      rwB1 = rW[R1 * RL_S + tx + 16];
            s0[0] += rhA0 + rwA0;  s0[1] += rhA0 + rwB0;
            s0[2] += rhB0 + rwA0;  s0[3] += rhB0 + rwB0;
            s1[0] += rhA1 + rwA1;  s1[1] += rhA1 + rwB1;
            s1[2] += rhB1 + rwA1;  s1[3] += rhB1 + rwB1;

            float mx0 = fmaxf(fmaxf(s0[0], s0[1]), fmaxf(s0[2], s0[3]));
            float mx1 = fmaxf(fmaxf(s1[0], s1[1]), fmaxf(s1[2], s1[3]));
            mx0 = fmaxf(mx0, __shfl_xor_sync(0xffffffffu, mx0, 1));
            mx0 = fmaxf(mx0, __shfl_xor_sync(0xffffffffu, mx0, 2));
            mx0 = fmaxf(mx0, __shfl_xor_sync(0xffffffffu, mx0, 4));
            mx0 = fmaxf(mx0, __shfl_xor_sync(0xffffffffu, mx0, 8));
            mx1 = fmaxf(mx1, __shfl_xor_sync(0xffffffffu, mx1, 1));
            mx1 = fmaxf(mx1, __shfl_xor_sync(0xffffffffu, mx1, 2));
            mx1 = fmaxf(mx1, __shfl_xor_sync(0xffffffffu, mx1, 4));
            mx1 = fmaxf(mx1, __shfl_xor_sync(0xffffffffu, mx1, 8));

            float mn0 = fmaxf(rowm[2 * i], mx0);
            float mn1 = fmaxf(rowm[2 * i + 1], mx1);
            float al0 = ex2f(rowm[2 * i] - mn0);
            float al1 = ex2f(rowm[2 * i + 1] - mn1);
            rowm[2 * i] = mn0; rowm[2 * i + 1] = mn1;
            ull alp = pack2(al0, al1);
            Om[i][0] = mul2(Om[i][0], alp);
            Om[i][1] = mul2(Om[i][1], alp);
            Om[i][2] = mul2(Om[i][2], alp);
            Om[i][3] = mul2(Om[i][3], alp);

            float ps0 = 0.f, ps1 = 0.f;
            #pragma unroll
            for (int j = 0; j < 4; j++) {
                float p0 = ex2f(s0[j] - mn0);
                float p1 = ex2f(s1[j] - mn1);
                ps0 += p0; ps1 += p1;
                *(ull*)(KP + (tx + 16 * j) * KP_S + R0) = pack2(p0, p1);
            }
            rowl[2 * i]     = rowl[2 * i] * al0 + ps0;
            rowl[2 * i + 1] = rowl[2 * i + 1] * al1 + ps1;
        }
        __syncthreads();

        // ---- O += P V : O paired over m, Pt broadcast reads ----
        #pragma unroll 8
        for (int n = 0; n < 64; n++) {
            const float* vrow = Vs + n * VS_S + 2 * tx;
            float v0, v1, v2, v3;
            unpack2(*(const ull*)vrow,        v0, v1);
            unpack2(*(const ull*)(vrow + 32), v2, v3);
            ull d0 = pack2(v0, v0), d1 = pack2(v1, v1);
            ull d2 = pack2(v2, v2), d3 = pack2(v3, v3);
            const ull* pp = (const ull*)(KP + n * KP_S + mrow);
            ull p0 = pp[0], p1 = pp[1], p2 = pp[2], p3 = pp[3];
            fma2(Om[0][0], p0, d0); fma2(Om[0][1], p0, d1);
            fma2(Om[0][2], p0, d2); fma2(Om[0][3], p0, d3);
            fma2(Om[1][0], p1, d0); fma2(Om[1][1], p1, d1);
            fma2(Om[1][2], p1, d2); fma2(Om[1][3], p1, d3);
            fma2(Om[2][0], p2, d0); fma2(Om[2][1], p2, d1);
            fma2(Om[2][2], p2, d2); fma2(Om[2][3], p2, d3);
            fma2(Om[3][0], p3, d0); fma2(Om[3][1], p3, d1);
            fma2(Om[3][2], p3, d2); fma2(Om[3][3], p3, d3);
        }
    }

    // ---- finalize ----
    #pragma unroll
    for (int r = 0; r < 8; r++) {
        float l = rowl[r];
        l += __shfl_xor_sync(0xffffffffu, l, 1);
        l += __shfl_xor_sync(0xffffffffu, l, 2);
        l += __shfl_xor_sync(0xffffffffu, l, 4);
        l += __shfl_xor_sync(0xffffffffu, l, 8);
        rowl[r] = __fdividef(1.0f, l);
    }
    #pragma unroll
    for (int i = 0; i < 4; i++) {
        const float inv0 = rowl[2 * i], inv1 = rowl[2 * i + 1];
        float o00, o10, o01, o11, o02, o12, o03, o13;
        unpack2(Om[i][0], o00, o10);
        unpack2(Om[i][1], o01, o11);
        unpack2(Om[i][2], o02, o12);
        unpack2(Om[i][3], o03, o13);
        float* op0 = oh + (size_t)(m0 + mrow + 2 * i) * 1024 + 2 * tx;
        float* op1 = op0 + 1024;
        *(float2*)op0        = make_float2(o00 * inv0, o01 * inv0);
        *(float2*)(op0 + 32) = make_float2(o02 * inv0, o03 * inv0);
        *(float2*)op1        = make_float2(o10 * inv1, o11 * inv1);
        *(float2*)(op1 + 32) = make_float2(o12 * inv1, o13 * inv1);
    }
}

extern "C" void kernel_launch(void* const* d_in, const int* in_sizes, int n_in,
                              void* d_out, int out_size)
{
    const float* q   = (const float*)d_in[0];
    const float* k   = (const float*)d_in[1];
    const float* v   = (const float*)d_in[2];
    const float* rph = (const float*)d_in[3];
    const float* rpw = (const float*)d_in[4];
    float* out = (float*)d_out;

    dim3 rg(32, 64);
    rel_kernel<<<rg, 256>>>(q, rph, rpw);

    const int smem = (64 * QT_S + 64 * KP_S + 64 * VS_S + 64 * RL_S * 2) * 4; // 68096 B
    cudaFuncSetAttribute(flash_kernel, cudaFuncAttributeMaxDynamicSharedMemorySize, smem);
    dim3 grid(SEQ / 64, NBH);
    flash_kernel<<<grid, 128, smem>>>(q, k, v, out);
}

// round 10
// speedup vs baseline: 1.0175x; 1.0162x over previous
#include <cuda_runtime.h>

typedef unsigned long long ull;

#define SEQ   1024
#define NBH   64
#define LOG2E 1.4426950408889634f

// rel_h / rel_w logit tables, pre-scaled by log2(e): [bh][s][k], k in 0..31
__device__ __align__(16) float g_relH[(size_t)NBH * SEQ * 32];
__device__ __align__(16) float g_relW[(size_t)NBH * SEQ * 32];

// ---------- f32x2 helpers ----------
__device__ __forceinline__ ull pack2(float x, float y) {
    ull r; asm("mov.b64 %0, {%1,%2};" : "=l"(r) : "f"(x), "f"(y)); return r;
}
__device__ __forceinline__ void unpack2(ull p, float& x, float& y) {
    asm("mov.b64 {%0,%1}, %2;" : "=f"(x), "=f"(y) : "l"(p));
}
__device__ __forceinline__ void fma2(ull& d, ull a, ull b) {
    asm("fma.rn.f32x2 %0, %1, %2, %0;" : "+l"(d) : "l"(a), "l"(b));
}
__device__ __forceinline__ ull mul2(ull a, ull b) {
    ull r; asm("mul.rn.f32x2 %0, %1, %2;" : "=l"(r) : "l"(a), "l"(b)); return r;
}
__device__ __forceinline__ float ex2f(float x) {
    float r; asm("ex2.approx.f32 %0, %1;" : "=f"(r) : "f"(x)); return r;
}

// ---------- kernel A: rel_h / rel_w precompute (smem-staged, tiled) ----------
__global__ void __launch_bounds__(256) rel_kernel(
    const float* __restrict__ q,
    const float* __restrict__ rph,
    const float* __restrict__ rpw)
{
    __shared__ float sQ[32 * 68];
    __shared__ float sRh[32 * 68];
    __shared__ float sRw[63 * 68];

    const int tid = threadIdx.x;
    const int h  = blockIdx.x;
    const int bh = blockIdx.y;
    const int b = bh >> 4, hd = bh & 15;

    {
        const int w = tid >> 3, c0 = (tid & 7) * 8;
        const float4* src = (const float4*)(q + ((size_t)(b * SEQ + h * 32 + w) * 16 + hd) * 64 + c0);
        *(float4*)(sQ + w * 68 + c0)     = src[0];
        *(float4*)(sQ + w * 68 + c0 + 4) = src[1];
        const float4* hs = (const float4*)(rph + (size_t)(h + 31 - w) * 64 + c0);
        *(float4*)(sRh + w * 68 + c0)     = hs[0];
        *(float4*)(sRh + w * 68 + c0 + 4) = hs[1];
    }
    for (int i = tid; i < 63 * 16; i += 256) {
        int r = i >> 4, c = (i & 15) * 4;
        *(float4*)(sRw + r * 68 + c) = *(const float4*)(rpw + (size_t)r * 64 + c);
    }
    __syncthreads();

    const int wid = tid >> 5, lane = tid & 31;   // lane = k
    #pragma unroll
    for (int rr = 0; rr < 4; rr++) {
        const int w = wid * 4 + rr;
        const float4* qv = (const float4*)(sQ + w * 68);
        const float4* hv = (const float4*)(sRh + lane * 68);
        const float4* wv = (const float4*)(sRw + (w + 31 - lane) * 68);
        float ah = 0.f, aw = 0.f;
        #pragma unroll
        for (int f = 0; f < 16; f++) {
            float4 a = qv[f], x = hv[f], y = wv[f];
            ah += a.x * x.x + a.y * x.y + a.z * x.z + a.w * x.w;
            aw += a.x * y.x + a.y * y.y + a.z * y.z + a.w * y.w;
        }
        size_t o = ((size_t)bh * SEQ + h * 32 + w) * 32 + lane;
        g_relH[o] = ah * LOG2E;
        g_relW[o] = aw * LOG2E;
    }
}

// ---------- kernel B: fp32 flash attention, BLOCK_N=32, 4 CTAs/SM ----------
// block 128 (tx 0..15, ty 0..7); thread tile 8 m-rows x 2 n-cols (n = tx+16j),
// d-cols = {2tx,2tx+1, 2tx+32,2tx+33}. S paired over m; O paired over m;
// P stored TRANSPOSED Pt[n][m] as ull pairs.
#define QT_S 64
#define KP_S 66
#define VS_S 66
#define RL_S 34
#define BN   32

__global__ void __launch_bounds__(128, 4)
flash_kernel(const float* __restrict__ q, const float* __restrict__ k,
             const float* __restrict__ v, float* __restrict__ out)
{
    extern __shared__ float sm[];
    float* Qt = sm;                     // [64][64]  Qt[c][m] * 0.125*log2e
    float* KP = Qt + 64 * QT_S;         // [32][66]  K[n][c] in QK, Pt[n][m] in PV
    float* Vs = KP + BN * KP_S;         // [32][66]  V[n][d]
    float* rH = Vs + BN * VS_S;         // [64][34]
    float* rW = rH + 64 * RL_S;         // [64][34]

    const int tid = threadIdx.x;
    const int tx = tid & 15, ty = tid >> 4;
    const int mrow = ty << 3;
    const int m0 = blockIdx.x << 6;
    const int bh = blockIdx.y;
    const int b = bh >> 4, hd = bh & 15;

    const size_t hoff = (size_t)b * SEQ * 1024 + (size_t)hd * 64;
    const float* qh = q + hoff;
    const float* kh = k + hoff;
    const float* vh = v + hoff;
    float*       oh = out + hoff;

    // ---- load Q tile transposed (scaled) + rel tables ----
    {
        const int lr = tid & 63;
        const int lc = (tid >> 6) * 32;
        const float qs = 0.125f * LOG2E;
        const float4* src = (const float4*)(qh + (size_t)(m0 + lr) * 1024 + lc);
        #pragma unroll
        for (int f = 0; f < 8; f++) {
            float4 x = src[f];
            const int c = lc + 4 * f;
            Qt[(c + 0) * QT_S + lr] = x.x * qs;
            Qt[(c + 1) * QT_S + lr] = x.y * qs;
            Qt[(c + 2) * QT_S + lr] = x.z * qs;
            Qt[(c + 3) * QT_S + lr] = x.w * qs;
        }
        const float4* rh4 = (const float4*)(g_relH + ((size_t)bh * SEQ + m0) * 32);
        const float4* rw4 = (const float4*)(g_relW + ((size_t)bh * SEQ + m0) * 32);
        #pragma unroll
        for (int f = 0; f < 4; f++) {
            const int gi = tid + f * 128;         // float4 index within 64x32
            const int m = gi >> 3, c4 = (gi & 7) * 4;
            float4 xh = rh4[gi];
            float4 xw = rw4[gi];
            rH[m * RL_S + c4 + 0] = xh.x; rH[m * RL_S + c4 + 1] = xh.y;
            rH[m * RL_S + c4 + 2] = xh.z; rH[m * RL_S + c4 + 3] = xh.w;
            rW[m * RL_S + c4 + 0] = xw.x; rW[m * RL_S + c4 + 1] = xw.y;
            rW[m * RL_S + c4 + 2] = xw.z; rW[m * RL_S + c4 + 3] = xw.w;
        }
    }

    // O accumulator: Om[mpair i][d-index u], ull lanes = rows (2i, 2i+1)
    ull   Om[4][4];
    float rowm[8], rowl[8];
    #pragma unroll
    for (int i = 0; i < 4; i++) {
        Om[i][0] = 0ull; Om[i][1] = 0ull; Om[i][2] = 0ull; Om[i][3] = 0ull;
    }
    #pragma unroll
    for (int r = 0; r < 8; r++) { rowm[r] = -3.0e38f; rowl[r] = 0.f; }

    const int lrow = tid >> 2;            // loader row (0..31)
    const int lcol = (tid & 3) << 4;      // loader col base (0,16,32,48)

    for (int n0 = 0; n0 < SEQ; n0 += BN) {
        __syncthreads();   // prev PV done with KP/Vs (iter 0: Qt/rel stores)
        // ---- load K[n][c] (stride 66) + V[n][d] (stride 66), float2 stores ----
        {
            const float4* ks  = (const float4*)(kh + (size_t)(n0 + lrow) * 1024 + lcol);
            const float4* vs4 = (const float4*)(vh + (size_t)(n0 + lrow) * 1024 + lcol);
            float* kd = KP + lrow * KP_S + lcol;
            float* vd = Vs + lrow * VS_S + lcol;
            #pragma unroll
            for (int f = 0; f < 4; f++) {
                float4 kx = ks[f];
                float4 vx = vs4[f];
                *(float2*)(kd + 4 * f)     = make_float2(kx.x, kx.y);
                *(float2*)(kd + 4 * f + 2) = make_float2(kx.z, kx.w);
                *(float2*)(vd + 4 * f)     = make_float2(vx.x, vx.y);
                *(float2*)(vd + 4 * f + 2) = make_float2(vx.z, vx.w);
            }
        }
        __syncthreads();

        // ---- S = Qs K^T : 8m x 2n, f32x2 paired over m, c-blocked by 2 ----
        ull Sa[4][2];
        #pragma unroll
        for (int i = 0; i < 4; i++) { Sa[i][0] = 0ull; Sa[i][1] = 0ull; }

        #pragma unroll 4
        for (int c = 0; c < 64; c += 2) {
            const ulonglong2* qp0 = (const ulonglong2*)(Qt + c * QT_S + mrow);
            const ulonglong2* qp1 = (const ulonglong2*)(Qt + (c + 1) * QT_S + mrow);
            ulonglong2 qA0 = qp0[0], qB0 = qp0[1];
            ulonglong2 qA1 = qp1[0], qB1 = qp1[1];
            const float* kp = KP + tx * KP_S + c;
            #pragma unroll
            for (int j = 0; j < 2; j++) {
                float2 kv = *(const float2*)(kp + 16 * j * KP_S);   // K[tx+16j][c..c+1]
                ull b0 = pack2(kv.x, kv.x);
                ull b1 = pack2(kv.y, kv.y);
                fma2(Sa[0][j], qA0.x, b0);
                fma2(Sa[1][j], qA0.y, b0);
                fma2(Sa[2][j], qB0.x, b0);
                fma2(Sa[3][j], qB0.y, b0);
                fma2(Sa[0][j], qA1.x, b1);
                fma2(Sa[1][j], qA1.y, b1);
                fma2(Sa[2][j], qB1.x, b1);
                fma2(Sa[3][j], qB1.y, b1);
            }
        }

        __syncthreads();   // all threads done reading KP as K

        // ---- softmax (2 rows at a time) + Pt store (transposed, ull pairs) ----
        const int kh0 = n0 >> 5;   // constant for whole tile (BN=32 aligned)
        #pragma unroll
        for (int i = 0; i < 4; i++) {
            float s0[2], s1[2];
            unpack2(Sa[i][0], s0[0], s1[0]);
            unpack2(Sa[i][1], s0[1], s1[1]);
            const int R0 = mrow + 2 * i, R1 = R0 + 1;
            // cols j=0,1 -> n = tx+16j: kw = tx + 16j, kh = kh0
            const float rh0 = rH[R0 * RL_S + kh0];
            const float rh1 = rH[R1 * RL_S + kh0];
            const float rwA0 = rW[R0 * RL_S + tx], rwB0 = rW[R0 * RL_S + tx + 16];
            const float rwA1 = rW[R1 * RL_S + tx], rwB1 = rW[R1 * RL_S + tx + 16];
            s0[0] += rh0 + rwA0;  s0[1] += rh0 + rwB0;
            s1[0] += rh1 + rwA1;  s1[1] += rh1 + rwB1;

            float mx0 = fmaxf(s0[0], s0[1]);
            float mx1 = fmaxf(s1[0], s1[1]);
            mx0 = fmaxf(mx0, __shfl_xor_sync(0xffffffffu, mx0, 1));
            mx0 = fmaxf(mx0, __shfl_xor_sync(0xffffffffu, mx0, 2));
            mx0 = fmaxf(mx0, __shfl_xor_sync(0xffffffffu, mx0, 4));
            mx0 = fmaxf(mx0, __shfl_xor_sync(0xffffffffu, mx0, 8));
            mx1 = fmaxf(mx1, __shfl_xor_sync(0xffffffffu, mx1, 1));
            mx1 = fmaxf(mx1, __shfl_xor_sync(0xffffffffu, mx1, 2));
            mx1 = fmaxf(mx1, __shfl_xor_sync(0xffffffffu, mx1, 4));
            mx1 = fmaxf(mx1, __shfl_xor_sync(0xffffffffu, mx1, 8));

            float mn0 = fmaxf(rowm[2 * i], mx0);
            float mn1 = fmaxf(rowm[2 * i + 1], mx1);
            float al0 = ex2f(rowm[2 * i] - mn0);
            float al1 = ex2f(rowm[2 * i + 1] - mn1);
            rowm[2 * i] = mn0; rowm[2 * i + 1] = mn1;
            ull alp = pack2(al0, al1);
            Om[i][0] = mul2(Om[i][0], alp);
            Om[i][1] = mul2(Om[i][1], alp);
            Om[i][2] = mul2(Om[i][2], alp);
            Om[i][3] = mul2(Om[i][3], alp);

            float p00 = ex2f(s0[0] - mn0);
            float p10 = ex2f(s1[0] - mn1);
            float p01 = ex2f(s0[1] - mn0);
            float p11 = ex2f(s1[1] - mn1);
            *(ull*)(KP + tx * KP_S + R0)        = pack2(p00, p10);
            *(ull*)(KP + (tx + 16) * KP_S + R0) = pack2(p01, p11);
            rowl[2 * i]     = rowl[2 * i] * al0 + p00 + p01;
            rowl[2 * i + 1] = rowl[2 * i + 1] * al1 + p10 + p11;
        }
        __syncthreads();

        // ---- O += P V : O paired over m, Pt broadcast reads ----
        #pragma unroll 8
        for (int n = 0; n < BN; n++) {
            const float* vrow = Vs + n * VS_S + 2 * tx;
            float v0, v1, v2, v3;
            unpack2(*(const ull*)vrow,        v0, v1);
            unpack2(*(const ull*)(vrow + 32), v2, v3);
            ull d0 = pack2(v0, v0), d1 = pack2(v1, v1);
            ull d2 = pack2(v2, v2), d3 = pack2(v3, v3);
            const ull* pp = (const ull*)(KP + n * KP_S + mrow);
            ull p0 = pp[0], p1 = pp[1], p2 = pp[2], p3 = pp[3];
            fma2(Om[0][0], p0, d0); fma2(Om[0][1], p0, d1);
            fma2(Om[0][2], p0, d2); fma2(Om[0][3], p0, d3);
            fma2(Om[1][0], p1, d0); fma2(Om[1][1], p1, d1);
            fma2(Om[1][2], p1, d2); fma2(Om[1][3], p1, d3);
            fma2(Om[2][0], p2, d0); fma2(Om[2][1], p2, d1);
            fma2(Om[2][2], p2, d2); fma2(Om[2][3], p2, d3);
            fma2(Om[3][0], p3, d0); fma2(Om[3][1], p3, d1);
            fma2(Om[3][2], p3, d2); fma2(Om[3][3], p3, d3);
        }
    }

    // ---- finalize ----
    #pragma unroll
    for (int r = 0; r < 8; r++) {
        float l = rowl[r];
        l += __shfl_xor_sync(0xffffffffu, l, 1);
        l += __shfl_xor_sync(0xffffffffu, l, 2);
        l += __shfl_xor_sync(0xffffffffu, l, 4);
        l += __shfl_xor_sync(0xffffffffu, l, 8);
        rowl[r] = __fdividef(1.0f, l);
    }
    #pragma unroll
    for (int i = 0; i < 4; i++) {
        const float inv0 = rowl[2 * i], inv1 = rowl[2 * i + 1];
        float o00, o10, o01, o11, o02, o12, o03, o13;
        unpack2(Om[i][0], o00, o10);
        unpack2(Om[i][1], o01, o11);
        unpack2(Om[i][2], o02, o12);
        unpack2(Om[i][3], o03, o13);
        float* op0 = oh + (size_t)(m0 + mrow + 2 * i) * 1024 + 2 * tx;
        float* op1 = op0 + 1024;
        *(float2*)op0        = make_float2(o00 * inv0, o01 * inv0);
        *(float2*)(op0 + 32) = make_float2(o02 * inv0, o03 * inv0);
        *(float2*)op1        = make_float2(o10 * inv1, o11 * inv1);
        *(float2*)(op1 + 32) = make_float2(o12 * inv1, o13 * inv1);
    }
}

extern "C" void kernel_launch(void* const* d_in, const int* in_sizes, int n_in,
                              void* d_out, int out_size)
{
    const float* q   = (const float*)d_in[0];
    const float* k   = (const float*)d_in[1];
    const float* v   = (const float*)d_in[2];
    const float* rph = (const float*)d_in[3];
    const float* rpw = (const float*)d_in[4];
    float* out = (float*)d_out;

    dim3 rg(32, 64);
    rel_kernel<<<rg, 256>>>(q, rph, rpw);

    const int smem = (64 * QT_S + BN * KP_S + BN * VS_S + 64 * RL_S * 2) * 4; // 50688 B
    cudaFuncSetAttribute(flash_kernel, cudaFuncAttributeMaxDynamicSharedMemorySize, smem);
    dim3 grid(SEQ / 64, NBH);
    flash_kernel<<<grid, 128, smem>>>(q, k, v, out);
}

// round 11
// speedup vs baseline: 1.0357x; 1.0179x over previous
#include <cuda_runtime.h>

typedef unsigned long long ull;

#define SEQ   1024
#define NBH   64
#define LOG2E 1.4426950408889634f

// rel_h / rel_w logit tables, pre-scaled by log2(e): [bh][s][k], k in 0..31
__device__ __align__(16) float g_relH[(size_t)NBH * SEQ * 32];
__device__ __align__(16) float g_relW[(size_t)NBH * SEQ * 32];
// per-row (maxH+maxW [log2 units], |q_row|); per-head max ||k||
__device__ __align__(16) float2 g_rowB[(size_t)NBH * SEQ];
__device__ float g_knorm[NBH];

// ---------- f32x2 helpers ----------
__device__ __forceinline__ ull pack2(float x, float y) {
    ull r; asm("mov.b64 %0, {%1,%2};" : "=l"(r) : "f"(x), "f"(y)); return r;
}
__device__ __forceinline__ void unpack2(ull p, float& x, float& y) {
    asm("mov.b64 {%0,%1}, %2;" : "=f"(x), "=f"(y) : "l"(p));
}
__device__ __forceinline__ void fma2(ull& d, ull a, ull b) {
    asm("fma.rn.f32x2 %0, %1, %2, %0;" : "+l"(d) : "l"(a), "l"(b));
}
__device__ __forceinline__ float ex2f(float x) {
    float r; asm("ex2.approx.f32 %0, %1;" : "=f"(r) : "f"(x)); return r;
}

// ---------- kernel K: per-head max ||k_row|| ----------
__global__ void __launch_bounds__(256) knorm_kernel(const float* __restrict__ k)
{
    __shared__ float red[256];
    const int tid = threadIdx.x;
    const int bh = blockIdx.x;
    const int b = bh >> 4, hd = bh & 15;
    const size_t base = (size_t)b * SEQ * 1024 + (size_t)hd * 64;

    float mx = 0.f;
    #pragma unroll
    for (int it = 0; it < 4; it++) {
        const int s = tid + it * 256;
        const float4* kr = (const float4*)(k + base + (size_t)s * 1024);
        float sum = 0.f;
        #pragma unroll
        for (int f = 0; f < 16; f++) {
            float4 x = kr[f];
            sum += x.x * x.x + x.y * x.y + x.z * x.z + x.w * x.w;
        }
        mx = fmaxf(mx, sum);
    }
    red[tid] = mx;
    __syncthreads();
    #pragma unroll
    for (int off = 128; off > 0; off >>= 1) {
        if (tid < off) red[tid] = fmaxf(red[tid], red[tid + off]);
        __syncthreads();
    }
    if (tid == 0) g_knorm[bh] = sqrtf(red[0]);
}

// ---------- kernel A: rel_h / rel_w precompute + row bounds ----------
__global__ void __launch_bounds__(256) rel_kernel(
    const float* __restrict__ q,
    const float* __restrict__ rph,
    const float* __restrict__ rpw)
{
    __shared__ float sQ[32 * 68];
    __shared__ float sRh[32 * 68];
    __shared__ float sRw[63 * 68];

    const int tid = threadIdx.x;
    const int h  = blockIdx.x;
    const int bh = blockIdx.y;
    const int b = bh >> 4, hd = bh & 15;

    {
        const int w = tid >> 3, c0 = (tid & 7) * 8;
        const float4* src = (const float4*)(q + ((size_t)(b * SEQ + h * 32 + w) * 16 + hd) * 64 + c0);
        *(float4*)(sQ + w * 68 + c0)     = src[0];
        *(float4*)(sQ + w * 68 + c0 + 4) = src[1];
        const float4* hs = (const float4*)(rph + (size_t)(h + 31 - w) * 64 + c0);
        *(float4*)(sRh + w * 68 + c0)     = hs[0];
        *(float4*)(sRh + w * 68 + c0 + 4) = hs[1];
    }
    for (int i = tid; i < 63 * 16; i += 256) {
        int r = i >> 4, c = (i & 15) * 4;
        *(float4*)(sRw + r * 68 + c) = *(const float4*)(rpw + (size_t)r * 64 + c);
    }
    __syncthreads();

    const int wid = tid >> 5, lane = tid & 31;   // lane = k
    #pragma unroll
    for (int rr = 0; rr < 4; rr++) {
        const int w = wid * 4 + rr;
        const float4* qv = (const float4*)(sQ + w * 68);
        const float4* hv = (const float4*)(sRh + lane * 68);
        const float4* wv = (const float4*)(sRw + (w + 31 - lane) * 68);
        float ah = 0.f, aw = 0.f;
        #pragma unroll
        for (int f = 0; f < 16; f++) {
            float4 a = qv[f], x = hv[f], y = wv[f];
            ah += a.x * x.x + a.y * x.y + a.z * x.z + a.w * x.w;
            aw += a.x * y.x + a.y * y.y + a.z * y.z + a.w * y.w;
        }
        ah *= LOG2E;
        aw *= LOG2E;
        size_t o = ((size_t)bh * SEQ + h * 32 + w) * 32 + lane;
        g_relH[o] = ah;
        g_relW[o] = aw;

        // row bound pieces: max over lanes of ah, aw; |q_row|^2
        float q0 = sQ[w * 68 + lane], q1 = sQ[w * 68 + lane + 32];
        float qn = q0 * q0 + q1 * q1;
        #pragma unroll
        for (int msk = 16; msk > 0; msk >>= 1) {
            ah = fmaxf(ah, __shfl_xor_sync(0xffffffffu, ah, msk));
            aw = fmaxf(aw, __shfl_xor_sync(0xffffffffu, aw, msk));
            qn += __shfl_xor_sync(0xffffffffu, qn, msk);
        }
        if (lane == 0)
            g_rowB[(size_t)bh * SEQ + h * 32 + w] = make_float2(ah + aw, sqrtf(qn));
    }
}

// ---------- kernel B: fp32 flash attention, fixed-bound softmax ----------
// block 128 (tx 0..15, ty 0..7); thread tile 8 m-rows x 2 n-cols (n = tx+16j),
// d-cols = {2tx,2tx+1, 2tx+32,2tx+33}. S paired over m; O paired over m;
// P stored TRANSPOSED Pt[n][m] as ull pairs. No online max: p = 2^(s - M_row).
#define QT_S 64
#define KP_S 66
#define VS_S 66
#define RL_S 34
#define BN   32

__global__ void __launch_bounds__(128, 4)
flash_kernel(const float* __restrict__ q, const float* __restrict__ k,
             const float* __restrict__ v, float* __restrict__ out)
{
    extern __shared__ float sm[];
    float* Qt = sm;                     // [64][64]  Qt[c][m] * 0.125*log2e
    float* KP = Qt + 64 * QT_S;         // [32][66]  K[n][c] in QK, Pt[n][m] in PV
    float* Vs = KP + BN * KP_S;         // [32][66]  V[n][d]
    float* rH = Vs + BN * VS_S;         // [64][34]
    float* rW = rH + 64 * RL_S;         // [64][34]

    const int tid = threadIdx.x;
    const int tx = tid & 15, ty = tid >> 4;
    const int mrow = ty << 3;
    const int m0 = blockIdx.x << 6;
    const int bh = blockIdx.y;
    const int b = bh >> 4, hd = bh & 15;

    const size_t hoff = (size_t)b * SEQ * 1024 + (size_t)hd * 64;
    const float* qh = q + hoff;
    const float* kh = k + hoff;
    const float* vh = v + hoff;
    float*       oh = out + hoff;

    // ---- load Q tile transposed (scaled) + rel tables ----
    {
        const int lr = tid & 63;
        const int lc = (tid >> 6) * 32;
        const float qs = 0.125f * LOG2E;
        const float4* src = (const float4*)(qh + (size_t)(m0 + lr) * 1024 + lc);
        #pragma unroll
        for (int f = 0; f < 8; f++) {
            float4 x = src[f];
            const int c = lc + 4 * f;
            Qt[(c + 0) * QT_S + lr] = x.x * qs;
            Qt[(c + 1) * QT_S + lr] = x.y * qs;
            Qt[(c + 2) * QT_S + lr] = x.z * qs;
            Qt[(c + 3) * QT_S + lr] = x.w * qs;
        }
        const float4* rh4 = (const float4*)(g_relH + ((size_t)bh * SEQ + m0) * 32);
        const float4* rw4 = (const float4*)(g_relW + ((size_t)bh * SEQ + m0) * 32);
        #pragma unroll
        for (int f = 0; f < 4; f++) {
            const int gi = tid + f * 128;         // float4 index within 64x32
            const int m = gi >> 3, c4 = (gi & 7) * 4;
            float4 xh = rh4[gi];
            float4 xw = rw4[gi];
            rH[m * RL_S + c4 + 0] = xh.x; rH[m * RL_S + c4 + 1] = xh.y;
            rH[m * RL_S + c4 + 2] = xh.z; rH[m * RL_S + c4 + 3] = xh.w;
            rW[m * RL_S + c4 + 0] = xw.x; rW[m * RL_S + c4 + 1] = xw.y;
            rW[m * RL_S + c4 + 2] = xw.z; rW[m * RL_S + c4 + 3] = xw.w;
        }
    }

    // per-row fixed softmax bound M and running sum
    float rowM[8], rowl[8];
    {
        const float kn = g_knorm[bh] * (0.125f * LOG2E);
        const float2* rb = g_rowB + (size_t)bh * SEQ + m0 + mrow;
        #pragma unroll
        for (int r = 0; r < 8; r++) {
            float2 x = rb[r];
            rowM[r] = x.x + x.y * kn;
            rowl[r] = 0.f;
        }
    }

    // O accumulator: Om[mpair i][d-index u], ull lanes = rows (2i, 2i+1)
    ull Om[4][4];
    #pragma unroll
    for (int i = 0; i < 4; i++) {
        Om[i][0] = 0ull; Om[i][1] = 0ull; Om[i][2] = 0ull; Om[i][3] = 0ull;
    }

    const int lrow = tid >> 2;            // loader row (0..31)
    const int lcol = (tid & 3) << 4;      // loader col base (0,16,32,48)

    for (int n0 = 0; n0 < SEQ; n0 += BN) {
        __syncthreads();   // prev PV done with KP/Vs (iter 0: Qt/rel stores)
        // ---- load K[n][c] (stride 66) + V[n][d] (stride 66), float2 stores ----
        {
            const float4* ks  = (const float4*)(kh + (size_t)(n0 + lrow) * 1024 + lcol);
            const float4* vs4 = (const float4*)(vh + (size_t)(n0 + lrow) * 1024 + lcol);
            float* kd = KP + lrow * KP_S + lcol;
            float* vd = Vs + lrow * VS_S + lcol;
            #pragma unroll
            for (int f = 0; f < 4; f++) {
                float4 kx = ks[f];
                float4 vx = vs4[f];
                *(float2*)(kd + 4 * f)     = make_float2(kx.x, kx.y);
                *(float2*)(kd + 4 * f + 2) = make_float2(kx.z, kx.w);
                *(float2*)(vd + 4 * f)     = make_float2(vx.x, vx.y);
                *(float2*)(vd + 4 * f + 2) = make_float2(vx.z, vx.w);
            }
        }
        __syncthreads();

        // ---- S = Qs K^T : 8m x 2n, f32x2 paired over m, c-blocked by 2 ----
        ull Sa[4][2];
        #pragma unroll
        for (int i = 0; i < 4; i++) { Sa[i][0] = 0ull; Sa[i][1] = 0ull; }

        #pragma unroll 4
        for (int c = 0; c < 64; c += 2) {
            const ulonglong2* qp0 = (const ulonglong2*)(Qt + c * QT_S + mrow);
            const ulonglong2* qp1 = (const ulonglong2*)(Qt + (c + 1) * QT_S + mrow);
            ulonglong2 qA0 = qp0[0], qB0 = qp0[1];
            ulonglong2 qA1 = qp1[0], qB1 = qp1[1];
            const float* kp = KP + tx * KP_S + c;
            #pragma unroll
            for (int j = 0; j < 2; j++) {
                float2 kv = *(const float2*)(kp + 16 * j * KP_S);   // K[tx+16j][c..c+1]
                ull b0 = pack2(kv.x, kv.x);
                ull b1 = pack2(kv.y, kv.y);
                fma2(Sa[0][j], qA0.x, b0);
                fma2(Sa[1][j], qA0.y, b0);
                fma2(Sa[2][j], qB0.x, b0);
                fma2(Sa[3][j], qB0.y, b0);
                fma2(Sa[0][j], qA1.x, b1);
                fma2(Sa[1][j], qA1.y, b1);
                fma2(Sa[2][j], qB1.x, b1);
                fma2(Sa[3][j], qB1.y, b1);
            }
        }

        __syncthreads();   // all threads done reading KP as K

        // ---- softmax with fixed bound + Pt store (transposed, ull pairs) ----
        const int kh0 = n0 >> 5;   // constant for whole tile (BN=32 aligned)
        #pragma unroll
        for (int i = 0; i < 4; i++) {
            float s0[2], s1[2];
            unpack2(Sa[i][0], s0[0], s1[0]);
            unpack2(Sa[i][1], s0[1], s1[1]);
            const int R0 = mrow + 2 * i, R1 = R0 + 1;
            // cols j=0,1 -> n = tx+16j: kw = tx + 16j, kh = kh0
            const float c0 = rH[R0 * RL_S + kh0] - rowM[2 * i];
            const float c1 = rH[R1 * RL_S + kh0] - rowM[2 * i + 1];
            const float rwA0 = rW[R0 * RL_S + tx], rwB0 = rW[R0 * RL_S + tx + 16];
            const float rwA1 = rW[R1 * RL_S + tx], rwB1 = rW[R1 * RL_S + tx + 16];

            float p00 = ex2f(s0[0] + c0 + rwA0);
            float p01 = ex2f(s0[1] + c0 + rwB0);
            float p10 = ex2f(s1[0] + c1 + rwA1);
            float p11 = ex2f(s1[1] + c1 + rwB1);
            *(ull*)(KP + tx * KP_S + R0)        = pack2(p00, p10);
            *(ull*)(KP + (tx + 16) * KP_S + R0) = pack2(p01, p11);
            rowl[2 * i]     += p00 + p01;
            rowl[2 * i + 1] += p10 + p11;
        }
        __syncthreads();

        // ---- O += P V : O paired over m, Pt broadcast reads ----
        #pragma unroll 8
        for (int n = 0; n < BN; n++) {
            const float* vrow = Vs + n * VS_S + 2 * tx;
            float v0, v1, v2, v3;
            unpack2(*(const ull*)vrow,        v0, v1);
            unpack2(*(const ull*)(vrow + 32), v2, v3);
            ull d0 = pack2(v0, v0), d1 = pack2(v1, v1);
            ull d2 = pack2(v2, v2), d3 = pack2(v3, v3);
            const ull* pp = (const ull*)(KP + n * KP_S + mrow);
            ull p0 = pp[0], p1 = pp[1], p2 = pp[2], p3 = pp[3];
            fma2(Om[0][0], p0, d0); fma2(Om[0][1], p0, d1);
            fma2(Om[0][2], p0, d2); fma2(Om[0][3], p0, d3);
            fma2(Om[1][0], p1, d0); fma2(Om[1][1], p1, d1);
            fma2(Om[1][2], p1, d2); fma2(Om[1][3], p1, d3);
            fma2(Om[2][0], p2, d0); fma2(Om[2][1], p2, d1);
            fma2(Om[2][2], p2, d2); fma2(Om[2][3], p2, d3);
            fma2(Om[3][0], p3, d0); fma2(Om[3][1], p3, d1);
            fma2(Om[3][2], p3, d2); fma2(Om[3][3], p3, d3);
        }
    }

    // ---- finalize ----
    #pragma unroll
    for (int r = 0; r < 8; r++) {
        float l = rowl[r];
        l += __shfl_xor_sync(0xffffffffu, l, 1);
        l += __shfl_xor_sync(0xffffffffu, l, 2);
        l += __shfl_xor_sync(0xffffffffu, l, 4);
        l += __shfl_xor_sync(0xffffffffu, l, 8);
        rowl[r] = __fdividef(1.0f, l);
    }
    #pragma unroll
    for (int i = 0; i < 4; i++) {
        const float inv0 = rowl[2 * i], inv1 = rowl[2 * i + 1];
        float o00, o10, o01, o11, o02, o12, o03, o13;
        unpack2(Om[i][0], o00, o10);
        unpack2(Om[i][1], o01, o11);
        unpack2(Om[i][2], o02, o12);
        unpack2(Om[i][3], o03, o13);
        float* op0 = oh + (size_t)(m0 + mrow + 2 * i) * 1024 + 2 * tx;
        float* op1 = op0 + 1024;
        *(float2*)op0        = make_float2(o00 * inv0, o01 * inv0);
        *(float2*)(op0 + 32) = make_float2(o02 * inv0, o03 * inv0);
        *(float2*)op1        = make_float2(o10 * inv1, o11 * inv1);
        *(float2*)(op1 + 32) = make_float2(o12 * inv1, o13 * inv1);
    }
}

extern "C" void kernel_launch(void* const* d_in, const int* in_sizes, int n_in,
                              void* d_out, int out_size)
{
    const float* q   = (const float*)d_in[0];
    const float* k   = (const float*)d_in[1];
    const float* v   = (const float*)d_in[2];
    const float* rph = (const float*)d_in[3];
    const float* rpw = (const float*)d_in[4];
    float* out = (float*)d_out;

    knorm_kernel<<<NBH, 256>>>(k);

    dim3 rg(32, 64);
    rel_kernel<<<rg, 256>>>(q, rph, rpw);

    const int smem = (64 * QT_S + BN * KP_S + BN * VS_S + 64 * RL_S * 2) * 4; // 50688 B
    cudaFuncSetAttribute(flash_kernel, cudaFuncAttributeMaxDynamicSharedMemorySize, smem);
    dim3 grid(SEQ / 64, NBH);
    flash_kernel<<<grid, 128, smem>>>(q, k, v, out);
}